// round 17
// baseline (speedup 1.0000x reference)
#include <cuda_runtime.h>
#include <cuda_fp16.h>
#include <math.h>
#include <stdint.h>

#define TNUM 2048
#define DDIM 2048
#define FDIM 512
#define ENUM 16
#define TOPK 4
#define MT   128
#define SH0  (TNUM * TOPK + ENUM * MT)   // 10240
#define HROWS (SH0 + TNUM)               // 12288
#define MAXT (HROWS / MT)                // 96

// ---------------- device scratch -------------------------------------------
__device__ float g_comb_w[TNUM * TOPK];
__device__ int   g_topk[TNUM * TOPK];
__device__ int   g_counts[ENUM];
__device__ int   g_offsets[ENUM + 1];
__device__ int   g_token_list[HROWS];
__device__ float g_weight_list[HROWS];
__device__ int   g_pos_of[TNUM * TOPK];
__device__ int   g_tile_seg[MAXT];
__device__ int   g_tile_r0[MAXT];
__device__ int   g_ntiles;
__device__ __half g_partialh[(size_t)HROWS * DDIM];
// fp16 operands
__device__ __half g_Xh[(size_t)TNUM * DDIM];
__device__ __half g_Hh[(size_t)HROWS * FDIM];
__device__ __half g_Wgt[(size_t)ENUM * FDIM * DDIM];
__device__ __half g_Wut[(size_t)ENUM * FDIM * DDIM];
__device__ __half g_Wdt[(size_t)ENUM * DDIM * FDIM];
__device__ __half g_sWgt[(size_t)FDIM * DDIM];
__device__ __half g_sWut[(size_t)FDIM * DDIM];
__device__ __half g_sWdt[(size_t)DDIM * FDIM];

// ---------------- helpers ----------------------------------------------------
__device__ __forceinline__ uint32_t smem_u32(const void* p) {
    uint32_t a;
    asm("{ .reg .u64 t; cvta.to.shared.u64 t, %1; cvt.u32.u64 %0, t; }" : "=r"(a) : "l"(p));
    return a;
}
__device__ __forceinline__ void cpa16(uint32_t dst, const void* src, bool valid) {
    int sz = valid ? 16 : 0;
    asm volatile("cp.async.cg.shared.global [%0], [%1], 16, %2;"
                 :: "r"(dst), "l"(src), "r"(sz) : "memory");
}
#define CP_COMMIT() asm volatile("cp.async.commit_group;" ::: "memory")
#define CP_WAIT(n)  asm volatile("cp.async.wait_group %0;" :: "n"(n) : "memory")

#define MMA_F16(C, A, b0, b1)                                                   \
    asm volatile("mma.sync.aligned.m16n8k16.row.col.f32.f16.f16.f32 "           \
                 "{%0,%1,%2,%3}, {%4,%5,%6,%7}, {%8,%9}, {%0,%1,%2,%3};"        \
                 : "+f"((C)[0]), "+f"((C)[1]), "+f"((C)[2]), "+f"((C)[3])       \
                 : "r"((A)[0]), "r"((A)[1]), "r"((A)[2]), "r"((A)[3]),          \
                   "r"(b0), "r"(b1))

__device__ __forceinline__ float silu_mul(float g, float u) {
    return g / (1.f + expf(-g)) * u;
}

// ---------------- transpose tile body (XOR-swizzled, 64x64) ------------------
__device__ __forceinline__ void tr_tile(const float* __restrict__ src,
                                        __half* __restrict__ dst,
                                        int R, int C, int cb, int rb) {
    __shared__ float sm[64 * 64];
    int c0 = cb * 64, r0 = rb * 64;
    int tid = threadIdx.x;
    int lr = tid >> 4, lc4 = tid & 15;
    int perm_s = (2 * lc4) & 31;
#pragma unroll
    for (int p = 0; p < 4; p++) {
        int r = lr + p * 16;
        float4 v = *reinterpret_cast<const float4*>(&src[(size_t)(r0 + r) * C + c0 + lc4 * 4]);
        int rs = r ^ perm_s;
        sm[(lc4 * 4 + 0) * 64 + rs] = v.x;
        sm[(lc4 * 4 + 1) * 64 + rs] = v.y;
        sm[(lc4 * 4 + 2) * 64 + rs] = v.z;
        sm[(lc4 * 4 + 3) * 64 + rs] = v.w;
    }
    __syncthreads();
    int sc = tid >> 5, sr2 = tid & 31;
#pragma unroll
    for (int p = 0; p < 8; p++) {
        int c = sc + p * 8;
        int perm = (2 * (c >> 2)) & 31;
        float2 v = *reinterpret_cast<const float2*>(&sm[c * 64 + ((sr2 * 2) ^ perm)]);
        __half2 h = __floats2half2_rn(v.x, v.y);
        *reinterpret_cast<__half2*>(&dst[(size_t)(c0 + c) * R + r0 + sr2 * 2]) = h;
    }
}

// ---------------- prep A: Wg/Wu/sWg/sWu transposes + dispatch init -----------
__global__ void __launch_bounds__(256)
k_prep_gu(const float* __restrict__ Wg, const float* __restrict__ Wu,
          const float* __restrict__ sWg, const float* __restrict__ sWu) {
    __half *wgt, *wut, *swgt, *swut;
    asm("cvta.global.u64 %0, g_Wgt;"  : "=l"(wgt));
    asm("cvta.global.u64 %0, g_Wut;"  : "=l"(wut));
    asm("cvta.global.u64 %0, g_sWgt;" : "=l"(swgt));
    asm("cvta.global.u64 %0, g_sWut;" : "=l"(swut));

    int z = blockIdx.z;
    const float* src;
    __half* dst;
    if (z < 16)       { src = Wg + (size_t)z * DDIM * FDIM;        dst = wgt + (size_t)z * DDIM * FDIM; }
    else if (z == 16) { src = sWg;                                  dst = swgt; }
    else if (z < 33)  { src = Wu + (size_t)(z - 17) * DDIM * FDIM; dst = wut + (size_t)(z - 17) * DDIM * FDIM; }
    else              { src = sWu;                                  dst = swut; }

    if (z == 16) {
        int id = (blockIdx.y * gridDim.x + blockIdx.x) * blockDim.x + threadIdx.x;
        if (id < ENUM) g_counts[id] = 0;
        if (id < SH0) g_token_list[id] = -1;
        if (id < TNUM) g_token_list[SH0 + id] = id;
    }
    tr_tile(src, dst, DDIM, FDIM, blockIdx.x, blockIdx.y);
}

// ---------------- prep B: Wd/sWd transposes ----------------------------------
__global__ void __launch_bounds__(256)
k_prep_d(const float* __restrict__ Wd, const float* __restrict__ sWd) {
    __half *wdt, *swdt;
    asm("cvta.global.u64 %0, g_Wdt;"  : "=l"(wdt));
    asm("cvta.global.u64 %0, g_sWdt;" : "=l"(swdt));
    int z = blockIdx.z;
    const float* src = (z < 16) ? Wd + (size_t)z * FDIM * DDIM : sWd;
    __half* dst      = (z < 16) ? wdt + (size_t)z * FDIM * DDIM : swdt;
    tr_tile(src, dst, FDIM, DDIM, blockIdx.x, blockIdx.y);
}

// ---------------- router (+ X f32->fp16 conversion fused) --------------------
__global__ void k_router(const float* __restrict__ x,
                         const float* __restrict__ gate_w,
                         const float* __restrict__ sgw) {
    int t = blockIdx.x;
    const float* xr = x + (size_t)t * DDIM;
    __half* xh = g_Xh + (size_t)t * DDIM;
    float acc[17];
#pragma unroll
    for (int e = 0; e < 17; e++) acc[e] = 0.f;
    for (int d = threadIdx.x; d < DDIM; d += blockDim.x) {
        float xv = xr[d];
        xh[d] = __float2half_rn(xv);
#pragma unroll
        for (int e = 0; e < ENUM; e++) acc[e] += xv * gate_w[e * DDIM + d];
        acc[16] += xv * sgw[d];
    }
#pragma unroll
    for (int off = 16; off; off >>= 1)
#pragma unroll
        for (int e = 0; e < 17; e++) acc[e] += __shfl_down_sync(0xffffffffu, acc[e], off);
    __shared__ float red[17][4];
    int warp = threadIdx.x >> 5, lane = threadIdx.x & 31;
    if (lane == 0)
#pragma unroll
        for (int e = 0; e < 17; e++) red[e][warp] = acc[e];
    __syncthreads();
    if (threadIdx.x == 0) {
        float v[17];
#pragma unroll
        for (int e = 0; e < 17; e++) v[e] = red[e][0] + red[e][1] + red[e][2] + red[e][3];
        float lv[16];
#pragma unroll
        for (int e = 0; e < ENUM; e++) lv[e] = v[e];
        int idx[TOPK]; float lg[TOPK];
#pragma unroll
        for (int k = 0; k < TOPK; k++) {
            int bi = 0; float bv = lv[0];
#pragma unroll
            for (int e = 1; e < ENUM; e++) if (lv[e] > bv) { bv = lv[e]; bi = e; }
            idx[k] = bi; lg[k] = bv; lv[bi] = -1e30f;
        }
        float mx = lg[0], s = 0.f, w[TOPK];
#pragma unroll
        for (int k = 0; k < TOPK; k++) { w[k] = expf(lg[k] - mx); s += w[k]; }
        float inv = 1.f / s;
#pragma unroll
        for (int k = 0; k < TOPK; k++) {
            g_topk[t * TOPK + k]   = idx[k];
            g_comb_w[t * TOPK + k] = w[k] * inv;
            atomicAdd(&g_counts[idx[k]], 1);
        }
        g_weight_list[SH0 + t] = 1.f / (1.f + expf(-v[16]));
    }
}

// ---------------- dispatch: fused scan + scatter (one block) -----------------
__global__ void __launch_bounds__(512)
k_dispatch() {
    __shared__ int s_cur[ENUM];
    int tid = threadIdx.x;
    if (tid == 0) {
        int o = 0, nt = 0;
        for (int e = 0; e < ENUM; e++) {
            g_offsets[e] = o;
            s_cur[e] = o;
            int c = (g_counts[e] + MT - 1) & ~(MT - 1);
            for (int r = 0; r < c; r += MT) { g_tile_seg[nt] = e; g_tile_r0[nt] = o + r; nt++; }
            o += c;
        }
        g_offsets[ENUM] = o;
        for (int r = 0; r < TNUM; r += MT) { g_tile_seg[nt] = ENUM; g_tile_r0[nt] = SH0 + r; nt++; }
        g_ntiles = nt;
    }
    __syncthreads();
    for (int i = tid; i < TNUM * TOPK; i += 512) {
        int e = g_topk[i];
        int pos = atomicAdd(&s_cur[e], 1);
        g_token_list[pos]  = i / TOPK;
        g_weight_list[pos] = g_comb_w[i];
        g_pos_of[i]        = pos;
    }
}

// ---------------- SMEM geometry (4-stage pipelines) --------------------------
#define ROWB    80
#define ROWW    20
#define UA_BUF  (128 * ROWB)                 // 10240 B
#define UB_BUF  (64 * ROWB)                  // 5120 B
#define U_STG   (UA_BUF + 2 * UB_BUF)        // 20480 B per stage
#define U_SMEM  (4 * U_STG)                  // 81920 B
#define DB_BUF  (128 * ROWB)                 // 10240 B
#define D_STG   (UA_BUF + DB_BUF)            // 20480 B per stage
#define D_SMEM  (4 * D_STG)                  // 81920 B

// ---------------- upgate: H = silu(X@Wg) * (X@Wu)  (fp16 m16n8k16) -----------
__global__ void __launch_bounds__(256, 2)
k_upgate() {
    int ti = blockIdx.x;
    if (ti >= g_ntiles) return;
    int z  = g_tile_seg[ti];
    int r0 = g_tile_r0[ti];
    int f0 = blockIdx.y * 64;

    const __half* Wg = (z == ENUM) ? g_sWgt : g_Wgt + (size_t)z * FDIM * DDIM;
    const __half* Wu = (z == ENUM) ? g_sWut : g_Wut + (size_t)z * FDIM * DDIM;

    extern __shared__ char smc[];
    uint32_t smb = smem_u32(smc);
    __shared__ int s_tok[MT];

    int tid = threadIdx.x, lane = tid & 31;
    int warp = tid >> 5, wm = warp & 3, wf = warp >> 2;
    int g = lane >> 2, t = lane & 3;

    if (tid < MT) s_tok[tid] = g_token_list[r0 + tid];
    __syncthreads();

    float Cg[2][4][4], Cu[2][4][4];
#pragma unroll
    for (int mt = 0; mt < 2; mt++)
#pragma unroll
        for (int nt = 0; nt < 4; nt++)
#pragma unroll
            for (int q = 0; q < 4; q++) { Cg[mt][nt][q] = 0.f; Cu[mt][nt][q] = 0.f; }

#define U_LOAD(i)                                                               \
    do {                                                                        \
        uint32_t st_ = smb + ((i) & 3) * U_STG;                                 \
        uint32_t a_  = st_;                                                     \
        uint32_t bg_ = st_ + UA_BUF;                                            \
        uint32_t bu_ = st_ + UA_BUF + UB_BUF;                                   \
        _Pragma("unroll")                                                       \
        for (int p = 0; p < 2; p++) {                                           \
            int idx = tid + p * 256;                                            \
            int row = idx >> 2, ch = idx & 3;                                   \
            int tok = s_tok[row];                                               \
            cpa16(a_ + row * ROWB + ch * 16,                                    \
                  g_Xh + (size_t)(tok < 0 ? 0 : tok) * DDIM + (i) * 32 + ch * 8,\
                  tok >= 0);                                                    \
        }                                                                       \
        {                                                                       \
            int row = tid >> 2, ch = tid & 3;                                   \
            cpa16(bg_ + row * ROWB + ch * 16,                                   \
                  Wg + (size_t)(f0 + row) * DDIM + (i) * 32 + ch * 8, true);    \
            cpa16(bu_ + row * ROWB + ch * 16,                                   \
                  Wu + (size_t)(f0 + row) * DDIM + (i) * 32 + ch * 8, true);    \
        }                                                                       \
        CP_COMMIT();                                                            \
    } while (0)

    const int NIT = DDIM / 32;   // 64
    U_LOAD(0); U_LOAD(1); U_LOAD(2);
    for (int i = 0; i < NIT; i++) {
        if (i + 3 < NIT) U_LOAD(i + 3); else CP_COMMIT();
        CP_WAIT(3);
        __syncthreads();
        uint32_t stg = ((uint32_t)(i & 3)) * U_STG;
        const uint32_t* As32 = (const uint32_t*)(smc + stg);
        const uint32_t* Bg32 = (const uint32_t*)(smc + stg + UA_BUF);
        const uint32_t* Bu32 = (const uint32_t*)(smc + stg + UA_BUF + UB_BUF);
#pragma unroll
        for (int s2 = 0; s2 < 2; s2++) {
            int kw = s2 * 8 + t;
            uint32_t a[2][4];
#pragma unroll
            for (int mt = 0; mt < 2; mt++) {
                const uint32_t* ar = As32 + (wm * 32 + mt * 16 + g) * ROWW + kw;
                a[mt][0] = ar[0];
                a[mt][1] = ar[8 * ROWW];
                a[mt][2] = ar[4];
                a[mt][3] = ar[8 * ROWW + 4];
            }
#pragma unroll
            for (int nt = 0; nt < 4; nt++) {
                int n = wf * 32 + nt * 8 + g;
                const uint32_t* bp = Bg32 + n * ROWW + kw;
                uint32_t b0 = bp[0], b1 = bp[4];
                MMA_F16(Cg[0][nt], a[0], b0, b1);
                MMA_F16(Cg[1][nt], a[1], b0, b1);
                bp = Bu32 + n * ROWW + kw;
                b0 = bp[0]; b1 = bp[4];
                MMA_F16(Cu[0][nt], a[0], b0, b1);
                MMA_F16(Cu[1][nt], a[1], b0, b1);
            }
        }
        __syncthreads();
    }
#undef U_LOAD

#pragma unroll
    for (int mt = 0; mt < 2; mt++) {
        int m0 = r0 + wm * 32 + mt * 16 + g;
#pragma unroll
        for (int nt = 0; nt < 4; nt++) {
            int fb = f0 + wf * 32 + nt * 8 + 2 * t;
            __half2 h;
            h = __floats2half2_rn(silu_mul(Cg[mt][nt][0], Cu[mt][nt][0]),
                                  silu_mul(Cg[mt][nt][1], Cu[mt][nt][1]));
            *reinterpret_cast<__half2*>(g_Hh + (size_t)m0 * FDIM + fb) = h;
            h = __floats2half2_rn(silu_mul(Cg[mt][nt][2], Cu[mt][nt][2]),
                                  silu_mul(Cg[mt][nt][3], Cu[mt][nt][3]));
            *reinterpret_cast<__half2*>(g_Hh + (size_t)(m0 + 8) * FDIM + fb) = h;
        }
    }
}

// ---------------- down: partial = w * (H @ Wd)  (fp16 m16n8k16) --------------
__global__ void __launch_bounds__(256, 2)
k_down() {
    int ti = blockIdx.x;
    if (ti >= g_ntiles) return;
    int z  = g_tile_seg[ti];
    int r0 = g_tile_r0[ti];
    int n0 = blockIdx.y * 128;

    const __half* Wd = (z == ENUM) ? g_sWdt : g_Wdt + (size_t)z * DDIM * FDIM;

    extern __shared__ char smc[];
    uint32_t smb = smem_u32(smc);

    int tid = threadIdx.x, lane = tid & 31;
    int warp = tid >> 5, wm = warp & 3, wn = warp >> 2;
    int g = lane >> 2, t = lane & 3;

    float C[2][8][4];
#pragma unroll
    for (int mt = 0; mt < 2; mt++)
#pragma unroll
        for (int nt = 0; nt < 8; nt++)
#pragma unroll
            for (int q = 0; q < 4; q++) C[mt][nt][q] = 0.f;

#define D_LOAD(i)                                                               \
    do {                                                                        \
        uint32_t st_ = smb + ((i) & 3) * D_STG;                                 \
        uint32_t a_ = st_;                                                      \
        uint32_t b_ = st_ + UA_BUF;                                             \
        _Pragma("unroll")                                                       \
        for (int p = 0; p < 2; p++) {                                           \
            int idx = tid + p * 256;                                            \
            int row = idx >> 2, ch = idx & 3;                                   \
            cpa16(a_ + row * ROWB + ch * 16,                                    \
                  g_Hh + (size_t)(r0 + row) * FDIM + (i) * 32 + ch * 8, true);  \
            cpa16(b_ + row * ROWB + ch * 16,                                    \
                  Wd + (size_t)(n0 + row) * FDIM + (i) * 32 + ch * 8, true);    \
        }                                                                       \
        CP_COMMIT();                                                            \
    } while (0)

    const int NIT = FDIM / 32;   // 16
    D_LOAD(0); D_LOAD(1); D_LOAD(2);
    for (int i = 0; i < NIT; i++) {
        if (i + 3 < NIT) D_LOAD(i + 3); else CP_COMMIT();
        CP_WAIT(3);
        __syncthreads();
        uint32_t stg = ((uint32_t)(i & 3)) * D_STG;
        const uint32_t* As32 = (const uint32_t*)(smc + stg);
        const uint32_t* Bs32 = (const uint32_t*)(smc + stg + UA_BUF);
#pragma unroll
        for (int s2 = 0; s2 < 2; s2++) {
            int kw = s2 * 8 + t;
            uint32_t a[2][4];
#pragma unroll
            for (int mt = 0; mt < 2; mt++) {
                const uint32_t* ar = As32 + (wm * 32 + mt * 16 + g) * ROWW + kw;
                a[mt][0] = ar[0];
                a[mt][1] = ar[8 * ROWW];
                a[mt][2] = ar[4];
                a[mt][3] = ar[8 * ROWW + 4];
            }
#pragma unroll
            for (int nt = 0; nt < 8; nt++) {
                int n = wn * 64 + nt * 8 + g;
                const uint32_t* bp = Bs32 + n * ROWW + kw;
                uint32_t b0 = bp[0], b1 = bp[4];
                MMA_F16(C[0][nt], a[0], b0, b1);
                MMA_F16(C[1][nt], a[1], b0, b1);
            }
        }
        __syncthreads();
    }
#undef D_LOAD

#pragma unroll
    for (int mt = 0; mt < 2; mt++) {
        int m0 = r0 + wm * 32 + mt * 16 + g;
        float w0 = g_weight_list[m0];
        float w1 = g_weight_list[m0 + 8];
#pragma unroll
        for (int nt = 0; nt < 8; nt++) {
            int n = n0 + wn * 64 + nt * 8 + t * 2;
            *reinterpret_cast<__half2*>(g_partialh + (size_t)m0 * DDIM + n) =
                __floats2half2_rn(w0 * C[mt][nt][0], w0 * C[mt][nt][1]);
            *reinterpret_cast<__half2*>(g_partialh + (size_t)(m0 + 8) * DDIM + n) =
                __floats2half2_rn(w1 * C[mt][nt][2], w1 * C[mt][nt][3]);
        }
    }
}

// ---------------- combine: fp16 partials -> f32 out --------------------------
__global__ void __launch_bounds__(256)
k_combine(float* __restrict__ out) {
    int t = blockIdx.x;
    int p0 = g_pos_of[t * TOPK + 0];
    int p1 = g_pos_of[t * TOPK + 1];
    int p2 = g_pos_of[t * TOPK + 2];
    int p3 = g_pos_of[t * TOPK + 3];
    const uint4* a0 = (const uint4*)(g_partialh + (size_t)p0 * DDIM);
    const uint4* a1 = (const uint4*)(g_partialh + (size_t)p1 * DDIM);
    const uint4* a2 = (const uint4*)(g_partialh + (size_t)p2 * DDIM);
    const uint4* a3 = (const uint4*)(g_partialh + (size_t)p3 * DDIM);
    const uint4* as = (const uint4*)(g_partialh + (size_t)(SH0 + t) * DDIM);

    int d = threadIdx.x;
    float2 acc[4];
#pragma unroll
    for (int j = 0; j < 4; j++) { acc[j].x = 0.f; acc[j].y = 0.f; }

    uint4 v;
    const __half2* h;
#define ACC(src)                                                                \
    do {                                                                        \
        v = (src)[d];                                                           \
        h = reinterpret_cast<const __half2*>(&v);                               \
        _Pragma("unroll")                                                       \
        for (int j = 0; j < 4; j++) {                                           \
            float2 f = __half22float2(h[j]);                                    \
            acc[j].x += f.x; acc[j].y += f.y;                                   \
        }                                                                       \
    } while (0)
    ACC(a0); ACC(a1); ACC(a2); ACC(a3); ACC(as);
#undef ACC

    float4 o0, o1;
    o0.x = acc[0].x; o0.y = acc[0].y; o0.z = acc[1].x; o0.w = acc[1].y;
    o1.x = acc[2].x; o1.y = acc[2].y; o1.z = acc[3].x; o1.w = acc[3].y;
    float4* op = (float4*)(out + (size_t)t * DDIM + d * 8);
    op[0] = o0;
    op[1] = o1;
}

// ---------------- launch ------------------------------------------------------
extern "C" void kernel_launch(void* const* d_in, const int* in_sizes, int n_in,
                              void* d_out, int out_size) {
    const float* x   = (const float*)d_in[0];
    const float* gw  = (const float*)d_in[1];
    const float* Wg  = (const float*)d_in[2];
    const float* Wu  = (const float*)d_in[3];
    const float* Wd  = (const float*)d_in[4];
    const float* sWg = (const float*)d_in[5];
    const float* sWu = (const float*)d_in[6];
    const float* sWd = (const float*)d_in[7];
    const float* sgw = (const float*)d_in[8];
    float* out = (float*)d_out;
    (void)in_sizes; (void)n_in; (void)out_size;

    cudaFuncSetAttribute(k_upgate, cudaFuncAttributeMaxDynamicSharedMemorySize, U_SMEM);
    cudaFuncSetAttribute(k_down,   cudaFuncAttributeMaxDynamicSharedMemorySize, D_SMEM);

    k_prep_gu <<<dim3(FDIM / 64, DDIM / 64, 34), 256>>>(Wg, Wu, sWg, sWu);   // 0
    k_prep_d  <<<dim3(DDIM / 64, FDIM / 64, 17), 256>>>(Wd, sWd);            // 1
    k_router  <<<TNUM, 128>>>(x, gw, sgw);                                    // 2
    k_dispatch<<<1, 512>>>();                                                 // 3
    k_upgate  <<<dim3(MAXT, FDIM / 64), 256, U_SMEM>>>();                     // 4
    k_down    <<<dim3(MAXT, DDIM / 128), 256, D_SMEM>>>();                    // 5
    k_combine <<<TNUM, 256>>>(out);                                           // 6
}